// round 8
// baseline (speedup 1.0000x reference)
#include <cuda_runtime.h>

// Problem constants
#define BB    16384
#define FF    64
#define RR    1024
#define CI    257      // 1 + F + F + P : [xatt 0..63][sq 64..127][inter 128..255][one 256]
#define TB    64       // batch tile per CTA
#define TR    64       // rule chunk
#define NCH   (RR / TR)   // 16
#define NT    512      // threads per CTA  (16 warps; 4 split-K groups of 128)

// C tile row stride: 64 rules + 4 pad = 68 floats (16B aligned rows)
#define CS    68

// Smem layout (floats)
#define OFF_PSM   0                        // [257][64]  = 16448
#define OFF_CPL   16448                    // [257][68]  = 17476 (unduplicated C chunk)
#define OFF_FIR   (16448 + 17476)          // [64][64]   = 4096
#define SMEM_FLOATS (OFF_FIR + 4096)       // 38020 floats = 152080 bytes

__device__ __forceinline__ void fma2(unsigned long long &d, unsigned long long a, unsigned long long b) {
    asm("fma.rn.f32x2 %0, %1, %2, %0;" : "+l"(d) : "l"(a), "l"(b));
}
__device__ __forceinline__ unsigned long long dup32(float c) {
    unsigned long long d;
    unsigned u = __float_as_uint(c);
    asm("mov.b64 %0, {%1, %1};" : "=l"(d) : "r"(u));
    return d;
}
__device__ __forceinline__ float2 up2(unsigned long long v) {
    float2 r;
    r.x = __uint_as_float((unsigned)(v & 0xFFFFFFFFull));
    r.y = __uint_as_float((unsigned)(v >> 32));
    return r;
}

extern "C" __global__ void __launch_bounds__(NT, 1)
anfis_fused_kernel(const float* __restrict__ x,
                   const float* __restrict__ aw,
                   const float* __restrict__ prm,
                   const float* __restrict__ thr,
                   const float* __restrict__ sgn,
                   const float* __restrict__ msk,
                   const float* __restrict__ Cq,
                   const int*   __restrict__ fidx,
                   const int*   __restrict__ ipair,
                   float* __restrict__ out)
{
    extern __shared__ float sm[];
    float* psm = sm + OFF_PSM;    // p[i][b]
    float* cpl = sm + OFF_CPL;    // cpl[i*CS + r] = C[r][i]  (unduplicated)
    float* fir = sm + OFF_FIR;    // fir[r_local][b]

    const int t   = threadIdx.x;
    const int cta = blockIdx.x;

    // ---------------- Phase A: x_att into psm (transposed) -------------------------
    {
        const float4* xg = reinterpret_cast<const float4*>(x + (size_t)cta * TB * FF);
        #pragma unroll
        for (int k = 0; k < 2; ++k) {
            int f4 = t + k * NT;          // 0..1023
            int bl = f4 >> 4;
            int fp = (f4 & 15) * 4;
            float4 v = xg[f4];
            psm[(fp + 0) * TB + bl] = v.x * aw[fp + 0];
            psm[(fp + 1) * TB + bl] = v.y * aw[fp + 1];
            psm[(fp + 2) * TB + bl] = v.z * aw[fp + 2];
            psm[(fp + 3) * TB + bl] = v.w * aw[fp + 3];
        }
    }
    __syncthreads();

    // ---------------- Phase B: squares, interactions, ones -------------------------
    #pragma unroll
    for (int k = 0; k < 8; ++k) {             // 4096 squares
        int e = t + k * NT;
        int f = e >> 6, b = e & 63;
        float v = psm[f * TB + b];
        psm[(64 + f) * TB + b] = v * v;
    }
    {
        const int2* ip2 = reinterpret_cast<const int2*>(ipair);
        #pragma unroll
        for (int k = 0; k < 16; ++k) {        // 8192 interaction entries
            int e = t + k * NT;
            int pi = e >> 6, b = e & 63;
            int2 pr = ip2[pi];
            psm[(128 + pi) * TB + b] = psm[pr.x * TB + b] * psm[pr.y * TB + b];
        }
    }
    if (t < TB) psm[256 * TB + t] = 1.0f;
    __syncthreads();

    // ---------------- Roles ---------------------------------------------------------
    // firing role: each thread handles 8 rules/chunk
    const int fb = t & 63;
    const int rg = t >> 6;                    // [0,8)
    // GEMM role: 4-way split-K. Group g = 128 threads = 8bq x 16rq grid, tile 8b x 4r.
    // Warp spans 4bq x 8rq -> pv spans 32 floats (1 phase), c spans 32 floats (1 phase).
    const int lane = t & 31;
    const int g    = t >> 7;                  // [0,4)
    const int wg   = (t >> 5) & 3;            // warp in group
    const int bq = ((wg & 1) << 2) | (lane & 3);        // [0,8)
    const int rq = ((wg >> 1) << 3) | (lane >> 2);      // [0,16)
    const int ibnd0[5] = {0, 65, 129, 193, 257};
    const int i0 = ibnd0[g];
    const int i1 = ibnd0[g + 1];

    float ssum = 0.0f;
    float yp0 = 0.f, yp1 = 0.f, yp2 = 0.f, yp3 = 0.f,
          yp4 = 0.f, yp5 = 0.f, yp6 = 0.f, yp7 = 0.f;

    const float4* th4 = reinterpret_cast<const float4*>(thr);
    const float4* sg4 = reinterpret_cast<const float4*>(sgn);
    const float4* mk4 = reinterpret_cast<const float4*>(msk);
    const int4*   fx4 = reinterpret_cast<const int4*>(fidx);

    // incremental (r,i) walk for the C producer (stride NT=512 over e = r*CI + i)
    const int pr0 = t / CI;
    const int pi0 = t - pr0 * CI;

    const float* pbase = psm + bq * 8;
    const float* cbase = cpl + rq * 4;

    for (int ch = 0; ch < NCH; ++ch) {
        // ---- Producer: C chunk -> unduplicated smem (coalesced scalar LDG) ----
        {
            const float* Cg = Cq + (size_t)ch * TR * CI;
            int r = pr0, i = pi0;
            for (int e = t; e < TR * CI; e += NT) {     // 33 iters
                float v = Cg[e];
                cpl[i * CS + r] = v;
                i += NT - CI; ++r;                      // e += 512: i += 255, r += 1
                if (i >= CI) { i -= CI; ++r; }          // possible second wrap
            }
        }
        // ---- Producer: firing for this rule chunk ----
        #pragma unroll
        for (int k = 0; k < 8; ++k) {
            int rl = rg * 8 + k;
            int r  = ch * TR + rl;
            int4   fi = fx4[r];
            float4 th = th4[r];
            float4 sg = sg4[r];
            float4 mk = mk4[r];
            float  pp = prm[r];
            float a0 = -pp * sg.x, a1 = -pp * sg.y, a2 = -pp * sg.z, a3 = -pp * sg.w;
            float e0 = __expf(a0 * (psm[fi.x * TB + fb] - th.x));
            float e1 = __expf(a1 * (psm[fi.y * TB + fb] - th.y));
            float e2 = __expf(a2 * (psm[fi.z * TB + fb] - th.z));
            float e3 = __expf(a3 * (psm[fi.w * TB + fb] - th.w));
            float t0 = fmaf(mk.x, e0, 1.0f);
            float t1 = fmaf(mk.y, e1, 1.0f);
            float t2 = fmaf(mk.z, e2, 1.0f);
            float t3 = fmaf(mk.w, e3, 1.0f);
            float f  = __fdividef(1.0f, (t0 * t1) * (t2 * t3));
            fir[rl * TB + fb] = f;
            ssum += f;
        }
        __syncthreads();   // cpl + fir ready

        // ---- Consumer: partial D[8b x 4r] over this group's i-range ----
        unsigned long long a00 = 0, a01 = 0, a02 = 0, a03 = 0,
                           a10 = 0, a11 = 0, a12 = 0, a13 = 0,
                           a20 = 0, a21 = 0, a22 = 0, a23 = 0,
                           a30 = 0, a31 = 0, a32 = 0, a33 = 0;
        #pragma unroll 2
        for (int i = i0; i < i1; ++i) {
            const float* pr = pbase + i * TB;
            ulonglong2 pva = *reinterpret_cast<const ulonglong2*>(pr);      // b pairs 0,1
            ulonglong2 pvb = *reinterpret_cast<const ulonglong2*>(pr + 4);  // b pairs 2,3
            float4 cv = *reinterpret_cast<const float4*>(cbase + i * CS);   // rules rq*4..+3
            unsigned long long c0 = dup32(cv.x);
            unsigned long long c1 = dup32(cv.y);
            unsigned long long c2 = dup32(cv.z);
            unsigned long long c3 = dup32(cv.w);
            fma2(a00, pva.x, c0); fma2(a01, pva.y, c0); fma2(a02, pvb.x, c0); fma2(a03, pvb.y, c0);
            fma2(a10, pva.x, c1); fma2(a11, pva.y, c1); fma2(a12, pvb.x, c1); fma2(a13, pvb.y, c1);
            fma2(a20, pva.x, c2); fma2(a21, pva.y, c2); fma2(a22, pvb.x, c2); fma2(a23, pvb.y, c2);
            fma2(a30, pva.x, c3); fma2(a31, pva.y, c3); fma2(a32, pvb.x, c3); fma2(a33, pvb.y, c3);
        }

        // ---- Epilogue: yp[b] += fir[r][b] * Dpartial[b][r] ----
        {
            const float* fbp = fir + bq * 8;
            #pragma unroll
            for (int k = 0; k < 4; ++k) {
                const float* fr = fbp + (rq * 4 + k) * TB;
                float4 fa = *reinterpret_cast<const float4*>(fr);
                float4 fc = *reinterpret_cast<const float4*>(fr + 4);
                unsigned long long b0 = (k == 0) ? a00 : (k == 1) ? a10 : (k == 2) ? a20 : a30;
                unsigned long long b1 = (k == 0) ? a01 : (k == 1) ? a11 : (k == 2) ? a21 : a31;
                unsigned long long b2 = (k == 0) ? a02 : (k == 1) ? a12 : (k == 2) ? a22 : a32;
                unsigned long long b3 = (k == 0) ? a03 : (k == 1) ? a13 : (k == 2) ? a23 : a33;
                float2 d0 = up2(b0), d1 = up2(b1), d2 = up2(b2), d3 = up2(b3);
                yp0 = fmaf(fa.x, d0.x, yp0); yp1 = fmaf(fa.y, d0.y, yp1);
                yp2 = fmaf(fa.z, d1.x, yp2); yp3 = fmaf(fa.w, d1.y, yp3);
                yp4 = fmaf(fc.x, d2.x, yp4); yp5 = fmaf(fc.y, d2.y, yp5);
                yp6 = fmaf(fc.z, d3.x, yp6); yp7 = fmaf(fc.w, d3.y, yp7);
            }
        }
        __syncthreads();   // before next chunk overwrites cpl/fir
    }

    // ---------------- Deterministic reductions (reuse psm region) -------------------
    // red: 64 slots (g*16+rq) x 64 b = 4096 floats at sm[0..4096); sred at sm[4096..4608)
    float* red  = sm;
    float* sred = sm + 4096;
    {
        int slot = g * 16 + rq;
        float* rp = red + slot * 64 + bq * 8;
        *reinterpret_cast<float4*>(rp)     = make_float4(yp0, yp1, yp2, yp3);
        *reinterpret_cast<float4*>(rp + 4) = make_float4(yp4, yp5, yp6, yp7);
    }
    sred[rg * 64 + fb] = ssum;
    __syncthreads();

    if (t < TB) {
        float ys = 0.0f;
        #pragma unroll
        for (int q = 0; q < 64; ++q) ys += red[q * 64 + t];
        float ss = 0.0f;
        #pragma unroll
        for (int q = 0; q < 8; ++q) ss += sred[q * 64 + t];
        out[cta * TB + t] = ys / (ss + 1e-8f);
    }
}

extern "C" void kernel_launch(void* const* d_in, const int* in_sizes, int n_in,
                              void* d_out, int out_size) {
    const float* x    = (const float*)d_in[0];
    const float* aw   = (const float*)d_in[1];
    const float* prm  = (const float*)d_in[2];
    const float* thr  = (const float*)d_in[3];
    const float* sgn  = (const float*)d_in[4];
    const float* msk  = (const float*)d_in[5];
    const float* Cq   = (const float*)d_in[6];
    const int*   fidx = (const int*)d_in[7];
    const int*   ip   = (const int*)d_in[8];
    float* out = (float*)d_out;

    const size_t smem_bytes = (size_t)SMEM_FLOATS * sizeof(float);
    cudaFuncSetAttribute(anfis_fused_kernel,
                         cudaFuncAttributeMaxDynamicSharedMemorySize,
                         (int)smem_bytes);

    anfis_fused_kernel<<<BB / TB, NT, smem_bytes>>>(x, aw, prm, thr, sgn, msk, Cq, fidx, ip, out);
}